// round 7
// baseline (speedup 1.0000x reference)
#include <cuda_runtime.h>
#include <cuda_fp16.h>
#include <cstdint>
#include <math.h>

#define BDIM 4096
#define DDIM 2048
#define KDIM 2048

// ---------------- device scratch ----------------
__device__ int    g_flags[2];              // [0] mem0 nonzero, [1] out0 nonzero
__device__ float  g_preA[BDIM * DDIM];
__device__ float  g_preB[BDIM * DDIM];
__device__ float  g_preC[BDIM * DDIM];
__device__ float  g_dec [BDIM * DDIM];
__device__ __half g_ax  [BDIM * KDIM];
__device__ __half g_ay  [BDIM * KDIM];
__device__ __half g_w0  [DDIM * KDIM];
__device__ __half g_w1  [DDIM * KDIM];
__device__ __half g_w2  [DDIM * KDIM];

struct GemmBatch {
    const __half* W[3];
    float*        C[3];
    const float*  b0[3];
    const float*  b1[3];
    const float*  b2[3];
    int           flagsel[3];   // bit0: need mem0!=0, bit1: need out0!=0
    int           accum;
};

struct ConvBatch {
    const float4* src[4];
    uint2*        dst[4];
    int           n4[4];
    int           flagsel[4];
};

__device__ __forceinline__ float sigmoidf_(float v) { return 1.0f / (1.0f + expf(-v)); }

__device__ __forceinline__ uint32_t smem_to_u32(const void* p) {
    uint32_t a;
    asm("{ .reg .u64 t; cvta.to.shared.u64 t, %1; cvt.u32.u64 %0, t; }" : "=r"(a) : "l"(p));
    return a;
}

__device__ __forceinline__ void cp16(uint32_t dst, const void* src) {
    asm volatile("cp.async.cg.shared.global [%0], [%1], 16;" :: "r"(dst), "l"(src) : "memory");
}
#define CP_COMMIT() asm volatile("cp.async.commit_group;" ::: "memory")

__device__ __forceinline__ void ldm_x4(uint32_t& r0, uint32_t& r1, uint32_t& r2, uint32_t& r3,
                                       uint32_t addr) {
    asm volatile("ldmatrix.sync.aligned.m8n8.x4.shared.b16 {%0,%1,%2,%3}, [%4];"
                 : "=r"(r0), "=r"(r1), "=r"(r2), "=r"(r3) : "r"(addr));
}

// fp16-accumulator MMA: d (2 regs of __half2) += a*b
__device__ __forceinline__ void mma_fp16acc(uint32_t* d,
                                            const uint32_t* a, const uint32_t* b) {
    asm volatile("mma.sync.aligned.m16n8k16.row.col.f16.f16.f16.f16 "
                 "{%0,%1}, {%2,%3,%4,%5}, {%6,%7}, {%0,%1};"
                 : "+r"(d[0]), "+r"(d[1])
                 : "r"(a[0]), "r"(a[1]), "r"(a[2]), "r"(a[3]), "r"(b[0]), "r"(b[1]));
}

__device__ __forceinline__ bool flag_ok(int flagsel) {
    if ((flagsel & 1) && g_flags[0] == 0) return false;
    if ((flagsel & 2) && g_flags[1] == 0) return false;
    return true;
}

// ---------------- flags ----------------
__global__ void reset_flags_kernel() { g_flags[0] = 0; g_flags[1] = 0; }

// fused: convert x -> fp16 AND scan mem0/out0 for nonzeros
__global__ void scanconv_kernel(const float4* __restrict__ x, uint2* __restrict__ ax,
                                const float4* __restrict__ m4, const float4* __restrict__ o4) {
    const int n4 = (BDIM * KDIM) / 4;
    for (int i = blockIdx.x * blockDim.x + threadIdx.x; i < n4; i += gridDim.x * blockDim.x) {
        float4 v = x[i];
        __half2 h0 = __floats2half2_rn(v.x, v.y);
        __half2 h1 = __floats2half2_rn(v.z, v.w);
        uint2 o;
        o.x = *(uint32_t*)&h0;
        o.y = *(uint32_t*)&h1;
        ax[i] = o;
    }
    const int total = (BDIM * DDIM) / 4;
    bool nzm = false, nzo = false;
    for (int i = blockIdx.x * blockDim.x + threadIdx.x; i < total; i += gridDim.x * blockDim.x) {
        float4 v = m4[i];
        nzm |= (v.x != 0.0f) | (v.y != 0.0f) | (v.z != 0.0f) | (v.w != 0.0f);
        float4 u = o4[i];
        nzo |= (u.x != 0.0f) | (u.y != 0.0f) | (u.z != 0.0f) | (u.w != 0.0f);
    }
    if (nzm) atomicOr(&g_flags[0], 1);
    if (nzo) atomicOr(&g_flags[1], 1);
}

// ---------------- batched fp32 -> fp16 conversion ----------------
__global__ void conv_batch_kernel(ConvBatch cb) {
    const int z = blockIdx.z;
    if (!flag_ok(cb.flagsel[z])) return;
    const float4* __restrict__ src = cb.src[z];
    uint2* __restrict__ dst = cb.dst[z];
    const int n4 = cb.n4[z];
    for (int i = blockIdx.x * blockDim.x + threadIdx.x; i < n4; i += gridDim.x * blockDim.x) {
        float4 v = src[i];
        __half2 h0 = __floats2half2_rn(v.x, v.y);
        __half2 h1 = __floats2half2_rn(v.z, v.w);
        uint2 o;
        o.x = *(uint32_t*)&h0;
        o.y = *(uint32_t*)&h1;
        dst[i] = o;
    }
}

// ---------------- fp16 mma.sync GEMM (fp16 accum per chunk, f32 across chunks) ----
// CTA tile 128(M) x 128(N) x 64(K); 8 warps = 2(M) x 4(N), warp tile 64x32.
// 3-stage cp.async pipeline, 2 CTAs/SM.
#define BK 64
#define CHUNKS (KDIM / BK)
#define CTAM 128
#define CTAN 128
#define STRB 144                            // bytes per k-row (64 halves + 8 pad)
#define A_BYTES (CTAM * STRB)               // 18432
#define B_BYTES (CTAN * STRB)               // 18432
#define STAGE_BYTES (A_BYTES + B_BYTES)     // 36864
#define NSTAGE 3
#define GEMM_SMEM (NSTAGE * STAGE_BYTES)    // 110592

__global__ __launch_bounds__(256, 2)
void gemm_fp16(const __half* __restrict__ A, GemmBatch gb, int epi_mode,
               const float* __restrict__ preA_in, float* __restrict__ outp,
               const float* __restrict__ bdec)
{
    const int z = blockIdx.z;
    if (!flag_ok(gb.flagsel[z])) return;
    const __half* __restrict__ W = gb.W[z];
    float* __restrict__ C = gb.C[z];

    extern __shared__ char smem[];
    const uint32_t sb0 = smem_to_u32(smem);

    const int tid = threadIdx.x;
    const int wid = tid >> 5;
    const int lane = tid & 31;
    const int g = lane >> 2;
    const int t = lane & 3;
    const int wm = wid & 1;       // 0..1
    const int wn = wid >> 1;      // 0..3
    const int bm = blockIdx.y * CTAM;
    const int bn = blockIdx.x * CTAN;

    float c[4][4][4];
    #pragma unroll
    for (int i = 0; i < 4; i++)
        #pragma unroll
        for (int j = 0; j < 4; j++)
            #pragma unroll
            for (int q = 0; q < 4; q++) c[i][j][q] = 0.0f;

    // ldmatrix per-lane addressing
    const uint32_t a_row = (uint32_t)(wm * 64 + (lane & 15));
    const uint32_t a_kb  = (uint32_t)((lane >> 4) * 16);
    const uint32_t b_row = (uint32_t)(wn * 32 + (lane & 7) + ((lane & 16) ? 8 : 0));
    const uint32_t b_kb  = (uint32_t)((lane & 8) ? 16 : 0);

    auto load_chunk = [&](int stage, int kt) {
        const uint32_t sb = sb0 + (uint32_t)stage * STAGE_BYTES;
        #pragma unroll
        for (int i = 0; i < 4; i++) {
            int gr = tid + i * 256;
            int row = gr >> 3, c8 = gr & 7;
            cp16(sb + (uint32_t)(row * STRB + c8 * 16),
                 A + (size_t)(bm + row) * KDIM + kt + c8 * 8);
        }
        #pragma unroll
        for (int i = 0; i < 4; i++) {
            int gr = tid + i * 256;
            int row = gr >> 3, c8 = gr & 7;
            cp16(sb + (uint32_t)(A_BYTES + row * STRB + c8 * 16),
                 W + (size_t)(bn + row) * KDIM + kt + c8 * 8);
        }
        CP_COMMIT();
    };

    load_chunk(0, 0);
    load_chunk(1, BK);

    int stage = 0;
    for (int ch = 0; ch < CHUNKS; ch++) {
        if (ch + 2 < CHUNKS) {
            int ns = stage + 2; if (ns >= NSTAGE) ns -= NSTAGE;
            load_chunk(ns, (ch + 2) * BK);
            asm volatile("cp.async.wait_group 2;" ::: "memory");
        } else if (ch + 1 < CHUNKS) {
            asm volatile("cp.async.wait_group 1;" ::: "memory");
        } else {
            asm volatile("cp.async.wait_group 0;" ::: "memory");
        }
        __syncthreads();

        const uint32_t As = sb0 + (uint32_t)stage * STAGE_BYTES;
        const uint32_t Bs = As + A_BYTES;

        // fp16 accumulators for this chunk
        uint32_t d16[4][4][2];
        #pragma unroll
        for (int mf = 0; mf < 4; mf++)
            #pragma unroll
            for (int nf = 0; nf < 4; nf++) { d16[mf][nf][0] = 0u; d16[mf][nf][1] = 0u; }

        #pragma unroll
        for (int s = 0; s < 4; s++) {
            const uint32_t kb = (uint32_t)(s * 32);
            uint32_t a[4][4];
            #pragma unroll
            for (int mf = 0; mf < 4; mf++)
                ldm_x4(a[mf][0], a[mf][1], a[mf][2], a[mf][3],
                       As + (a_row + mf * 16) * STRB + kb + a_kb);
            uint32_t b[4][2];
            #pragma unroll
            for (int nh = 0; nh < 2; nh++) {
                uint32_t r0, r1, r2, r3;
                ldm_x4(r0, r1, r2, r3, Bs + (b_row + nh * 16) * STRB + kb + b_kb);
                b[2 * nh][0] = r0;      b[2 * nh][1] = r1;
                b[2 * nh + 1][0] = r2;  b[2 * nh + 1][1] = r3;
            }
            #pragma unroll
            for (int mf = 0; mf < 4; mf++)
                #pragma unroll
                for (int nf = 0; nf < 4; nf++)
                    mma_fp16acc(d16[mf][nf], a[mf], b[nf]);
        }

        // promote chunk sums to fp32
        #pragma unroll
        for (int mf = 0; mf < 4; mf++)
            #pragma unroll
            for (int nf = 0; nf < 4; nf++) {
                __half2 h0 = *reinterpret_cast<__half2*>(&d16[mf][nf][0]);
                __half2 h1 = *reinterpret_cast<__half2*>(&d16[mf][nf][1]);
                float2 f0 = __half22float2(h0);
                float2 f1 = __half22float2(h1);
                c[mf][nf][0] += f0.x;
                c[mf][nf][1] += f0.y;
                c[mf][nf][2] += f1.x;
                c[mf][nf][3] += f1.y;
            }

        __syncthreads();
        if (++stage >= NSTAGE) stage = 0;
    }

    // ---- epilogue ----
    const float* b0 = gb.b0[z];
    const float* b1 = gb.b1[z];
    const float* b2 = gb.b2[z];
    const int accum = gb.accum;

    if (epi_mode == 0) {
        #pragma unroll
        for (int nf = 0; nf < 4; nf++) {
            const int col = bn + wn * 32 + nf * 8 + 2 * t;
            float bs0 = 0.0f, bs1 = 0.0f;
            if (!accum) {
                if (b0) { bs0 += b0[col]; bs1 += b0[col + 1]; }
                if (b1) { bs0 += b1[col]; bs1 += b1[col + 1]; }
                if (b2) { bs0 += b2[col]; bs1 += b2[col + 1]; }
            }
            #pragma unroll
            for (int mf = 0; mf < 4; mf++) {
                const int r = bm + wm * 64 + mf * 16 + g;
                float2 v0 = make_float2(c[mf][nf][0] + bs0, c[mf][nf][1] + bs1);
                float2 v1 = make_float2(c[mf][nf][2] + bs0, c[mf][nf][3] + bs1);
                float2* p0 = (float2*)(C + (size_t)r * DDIM + col);
                float2* p1 = (float2*)(C + (size_t)(r + 8) * DDIM + col);
                if (accum) {
                    float2 o0 = *p0, o1 = *p1;
                    v0.x += o0.x; v0.y += o0.y; v1.x += o1.x; v1.y += o1.y;
                }
                *p0 = v0;
                *p1 = v1;
            }
        }
    } else {
        // fused final (preB GEMM): fast path writes out directly, slow path stores raw preB
        const bool slow = (g_flags[0] | g_flags[1]) != 0;
        #pragma unroll
        for (int nf = 0; nf < 4; nf++) {
            const int col = bn + wn * 32 + nf * 8 + 2 * t;
            float bs0 = b0[col] + b1[col] + b2[col];
            float bs1 = b0[col + 1] + b1[col + 1] + b2[col + 1];
            float d0 = bdec[col], d1 = bdec[col + 1];
            #pragma unroll
            for (int mf = 0; mf < 4; mf++) {
                const int r = bm + wm * 64 + mf * 16 + g;
                float2 v0 = make_float2(c[mf][nf][0] + bs0, c[mf][nf][1] + bs1);
                float2 v1 = make_float2(c[mf][nf][2] + bs0, c[mf][nf][3] + bs1);
                if (slow) {
                    *(float2*)(C + (size_t)r * DDIM + col) = v0;
                    *(float2*)(C + (size_t)(r + 8) * DDIM + col) = v1;
                } else {
                    float2 pa0 = *(const float2*)(preA_in + (size_t)r * DDIM + col);
                    float2 pa1 = *(const float2*)(preA_in + (size_t)(r + 8) * DDIM + col);
                    float2 o0, o1;
                    o0.x = d0 + sigmoidf_(pa0.x) * sigmoidf_(v0.x);
                    o0.y = d1 + sigmoidf_(pa0.y) * sigmoidf_(v0.y);
                    o1.x = d0 + sigmoidf_(pa1.x) * sigmoidf_(v1.x);
                    o1.y = d1 + sigmoidf_(pa1.y) * sigmoidf_(v1.y);
                    *(float2*)(outp + (size_t)r * DDIM + col) = o0;
                    *(float2*)(outp + (size_t)(r + 8) * DDIM + col) = o1;
                }
            }
        }
    }
}

// ---------------- gated elementwise ----------------
__global__ void rgconv_kernel(const float4* __restrict__ mem0, uint2* __restrict__ ay) {
    if (g_flags[0] == 0) return;
    const int n4 = (BDIM * DDIM) / 4;
    const float4* __restrict__ pc = (const float4*)g_preC;
    for (int i = blockIdx.x * blockDim.x + threadIdx.x; i < n4; i += gridDim.x * blockDim.x) {
        float4 p = pc[i];
        float4 m = mem0[i];
        __half2 h0 = __floats2half2_rn(sigmoidf_(p.x) * m.x, sigmoidf_(p.y) * m.y);
        __half2 h1 = __floats2half2_rn(sigmoidf_(p.z) * m.z, sigmoidf_(p.w) * m.w);
        uint2 o;
        o.x = *(uint32_t*)&h0;
        o.y = *(uint32_t*)&h1;
        ay[i] = o;
    }
}

__global__ void final_kernel(float* __restrict__ out, const float* __restrict__ b_dec) {
    if (g_flags[0] == 0 && g_flags[1] == 0) return;
    const bool usemem = (g_flags[0] != 0);
    const int total = BDIM * DDIM;
    for (int i = blockIdx.x * blockDim.x + threadIdx.x; i < total; i += gridDim.x * blockDim.x) {
        float d = usemem ? g_dec[i] : b_dec[i & (DDIM - 1)];
        out[i] = d + sigmoidf_(g_preA[i]) * sigmoidf_(g_preB[i]);
    }
}

// ---------------- host orchestration ----------------
extern "C" void kernel_launch(void* const* d_in, const int* in_sizes, int n_in,
                              void* d_out, int out_size) {
    const float* x              = (const float*)d_in[0];
    const float* out0           = (const float*)d_in[1];
    const float* mem0           = (const float*)d_in[2];
    const float* w_inpgate      = (const float*)d_in[3];
    const float* b_inpgate      = (const float*)d_in[4];
    const float* w_rec_inpgate  = (const float*)d_in[5];
    const float* b_rec_inpgate  = (const float*)d_in[6];
    const float* w_mem_inpgate  = (const float*)d_in[7];
    const float* b_mem_inpgate  = (const float*)d_in[8];
    const float* w_inp          = (const float*)d_in[9];
    const float* b_inp          = (const float*)d_in[10];
    const float* w_rec_inp      = (const float*)d_in[11];
    const float* b_rec_inp      = (const float*)d_in[12];
    const float* w_readgate     = (const float*)d_in[13];
    const float* b_readgate     = (const float*)d_in[14];
    const float* w_rec_readgate = (const float*)d_in[15];
    const float* b_rec_readgate = (const float*)d_in[16];
    const float* w_mem_readgate = (const float*)d_in[17];
    const float* b_mem_readgate = (const float*)d_in[18];
    const float* w_decoder      = (const float*)d_in[19];
    const float* b_decoder      = (const float*)d_in[20];
    float* out = (float*)d_out;

    void *pA, *pB, *pC, *pD, *pax, *pay, *pw0, *pw1, *pw2;
    cudaGetSymbolAddress(&pA, g_preA); cudaGetSymbolAddress(&pB, g_preB);
    cudaGetSymbolAddress(&pC, g_preC); cudaGetSymbolAddress(&pD, g_dec);
    cudaGetSymbolAddress(&pax, g_ax);  cudaGetSymbolAddress(&pay, g_ay);
    cudaGetSymbolAddress(&pw0, g_w0);  cudaGetSymbolAddress(&pw1, g_w1);
    cudaGetSymbolAddress(&pw2, g_w2);
    float* preA = (float*)pA;  float* preB = (float*)pB;
    float* preC = (float*)pC;  float* dec  = (float*)pD;
    __half* ax = (__half*)pax; __half* ay = (__half*)pay;
    __half* w0h = (__half*)pw0; __half* w1h = (__half*)pw1; __half* w2h = (__half*)pw2;

    cudaFuncSetAttribute(gemm_fp16, cudaFuncAttributeMaxDynamicSharedMemorySize, GEMM_SMEM);

    const int nA4 = (BDIM * KDIM) / 4;
    const int nW4 = (DDIM * KDIM) / 4;
    const dim3 GRID1(DDIM / CTAN, BDIM / CTAM, 1);  // 16 x 32
    const dim3 GRID2(DDIM / CTAN, BDIM / CTAM, 2);
    const dim3 GRID3(DDIM / CTAN, BDIM / CTAM, 3);

    // 1) flags + convert x (fused)
    reset_flags_kernel<<<1, 1>>>();
    scanconv_kernel<<<2048, 256>>>((const float4*)x, (uint2*)ax,
                                   (const float4*)mem0, (const float4*)out0);

    // 2) convert the three x-side weights (ungated)
    {
        ConvBatch cb = {};
        cb.src[0] = (const float4*)w_inp;      cb.dst[0] = (uint2*)w0h; cb.n4[0] = nW4; cb.flagsel[0] = 0;
        cb.src[1] = (const float4*)w_inpgate;  cb.dst[1] = (uint2*)w1h; cb.n4[1] = nW4; cb.flagsel[1] = 0;
        cb.src[2] = (const float4*)w_readgate; cb.dst[2] = (uint2*)w2h; cb.n4[2] = nW4; cb.flagsel[2] = 0;
        conv_batch_kernel<<<dim3(512, 1, 3), 256>>>(cb);
    }

    // 3) GEMM batch: preA (always), preC (mem gated)
    {
        GemmBatch gb = {};
        gb.W[0] = w0h; gb.C[0] = preA; gb.b0[0] = b_inp;      gb.b1[0] = b_rec_inp;      gb.flagsel[0] = 0;
        gb.W[1] = w2h; gb.C[1] = preC; gb.b0[1] = b_readgate; gb.b1[1] = b_mem_readgate; gb.b2[1] = b_rec_readgate; gb.flagsel[1] = 1;
        gb.accum = 0;
        gemm_fp16<<<GRID2, 256, GEMM_SMEM>>>(ax, gb, 0, nullptr, nullptr, nullptr);
    }

    // 4) preB GEMM with fused final epilogue (fast path writes `out` directly)
    {
        GemmBatch gb = {};
        gb.W[0] = w1h; gb.C[0] = preB;
        gb.b0[0] = b_inpgate; gb.b1[0] = b_mem_inpgate; gb.b2[0] = b_rec_inpgate;
        gb.flagsel[0] = 0; gb.accum = 0;
        gemm_fp16<<<GRID1, 256, GEMM_SMEM>>>(ax, gb, 1, preA, out, b_decoder);
    }

    // 5) out0 recurrent terms  [out0 != 0]
    {
        ConvBatch cb = {};
        cb.src[0] = (const float4*)out0;            cb.dst[0] = (uint2*)ay;  cb.n4[0] = nA4; cb.flagsel[0] = 2;
        cb.src[1] = (const float4*)w_rec_inp;       cb.dst[1] = (uint2*)w0h; cb.n4[1] = nW4; cb.flagsel[1] = 2;
        cb.src[2] = (const float4*)w_rec_inpgate;   cb.dst[2] = (uint2*)w1h; cb.n4[2] = nW4; cb.flagsel[2] = 2;
        cb.src[3] = (const float4*)w_rec_readgate;  cb.dst[3] = (uint2*)w2h; cb.n4[3] = nW4; cb.flagsel[3] = 3;
        conv_batch_kernel<<<dim3(512, 1, 4), 256>>>(cb);
    }
    {
        GemmBatch gb = {};
        gb.W[0] = w0h; gb.C[0] = preA; gb.flagsel[0] = 2;
        gb.W[1] = w1h; gb.C[1] = preB; gb.flagsel[1] = 2;
        gb.W[2] = w2h; gb.C[2] = preC; gb.flagsel[2] = 3;
        gb.accum = 1;
        gemm_fp16<<<GRID3, 256, GEMM_SMEM>>>(ay, gb, 0, nullptr, nullptr, nullptr);
    }

    // 6) mem0 terms  [mem0 != 0]
    {
        ConvBatch cb = {};
        cb.src[0] = (const float4*)mem0;            cb.dst[0] = (uint2*)ay;  cb.n4[0] = nA4; cb.flagsel[0] = 1;
        cb.src[1] = (const float4*)w_mem_inpgate;   cb.dst[1] = (uint2*)w0h; cb.n4[1] = nW4; cb.flagsel[1] = 1;
        cb.src[2] = (const float4*)w_mem_readgate;  cb.dst[2] = (uint2*)w1h; cb.n4[2] = nW4; cb.flagsel[2] = 1;
        conv_batch_kernel<<<dim3(512, 1, 3), 256>>>(cb);
    }
    {
        GemmBatch gb = {};
        gb.W[0] = w0h; gb.C[0] = preB; gb.flagsel[0] = 1;
        gb.W[1] = w1h; gb.C[1] = preC; gb.flagsel[1] = 1;
        gb.accum = 1;
        gemm_fp16<<<GRID2, 256, GEMM_SMEM>>>(ay, gb, 0, nullptr, nullptr, nullptr);
    }

    // 7) ay = fp16(sigmoid(preC)*mem0), convert w_decoder, decoder GEMM  [mem0 != 0]
    rgconv_kernel<<<2048, 256>>>((const float4*)mem0, (uint2*)ay);
    {
        ConvBatch cb = {};
        cb.src[0] = (const float4*)w_decoder; cb.dst[0] = (uint2*)w0h; cb.n4[0] = nW4; cb.flagsel[0] = 1;
        conv_batch_kernel<<<dim3(512, 1, 1), 256>>>(cb);
    }
    {
        GemmBatch gb = {};
        gb.W[0] = w0h; gb.C[0] = dec; gb.b0[0] = b_decoder; gb.flagsel[0] = 1;
        gb.accum = 0;
        gemm_fp16<<<GRID1, 256, GEMM_SMEM>>>(ay, gb, 0, nullptr, nullptr, nullptr);
    }

    // 8) slow-path final (gated off when both states are zero)
    final_kernel<<<2048, 256>>>(out, b_decoder);
}

// round 8
// speedup vs baseline: 1.3257x; 1.3257x over previous
#include <cuda_runtime.h>
#include <cuda_fp16.h>
#include <cstdint>
#include <math.h>

#define BDIM 4096
#define DDIM 2048
#define KDIM 2048

// ---------------- device scratch ----------------
__device__ int    g_flags[2];              // [0] mem0 nonzero, [1] out0 nonzero
__device__ float  g_preA[BDIM * DDIM];
__device__ float  g_preB[BDIM * DDIM];
__device__ float  g_preC[BDIM * DDIM];
__device__ float  g_dec [BDIM * DDIM];
__device__ __half g_ax  [BDIM * KDIM];
__device__ __half g_ay  [BDIM * KDIM];
__device__ __half g_w0  [DDIM * KDIM];
__device__ __half g_w1  [DDIM * KDIM];
__device__ __half g_w2  [DDIM * KDIM];

struct GemmBatch {
    const __half* W[3];
    float*        C[3];
    const float*  b0[3];
    const float*  b1[3];
    const float*  b2[3];
    int           flagsel[3];   // bit0: need mem0!=0, bit1: need out0!=0
    int           accum;
};

struct PrepBatch {              // z-batched elementwise prep
    const float4* src[5];
    uint2*        dst[5];
    int           n4[5];
    int           mode[5];      // 0=conv, 1=scan(mem0=src,out0=dst-as-src2)
};

struct ConvBatch {
    const float4* src[4];
    uint2*        dst[4];
    int           n4[4];
    int           flagsel[4];
};

__device__ __forceinline__ float sigmoidf_(float v) { return 1.0f / (1.0f + expf(-v)); }

__device__ __forceinline__ uint32_t smem_to_u32(const void* p) {
    uint32_t a;
    asm("{ .reg .u64 t; cvta.to.shared.u64 t, %1; cvt.u32.u64 %0, t; }" : "=r"(a) : "l"(p));
    return a;
}

__device__ __forceinline__ void cp16(uint32_t dst, const void* src) {
    asm volatile("cp.async.cg.shared.global [%0], [%1], 16;" :: "r"(dst), "l"(src) : "memory");
}
#define CP_COMMIT() asm volatile("cp.async.commit_group;" ::: "memory")

__device__ __forceinline__ void ldm_x4(uint32_t& r0, uint32_t& r1, uint32_t& r2, uint32_t& r3,
                                       uint32_t addr) {
    asm volatile("ldmatrix.sync.aligned.m8n8.x4.shared.b16 {%0,%1,%2,%3}, [%4];"
                 : "=r"(r0), "=r"(r1), "=r"(r2), "=r"(r3) : "r"(addr));
}

__device__ __forceinline__ void mma_fp16(float* c, const uint32_t* a, const uint32_t* b) {
    asm volatile("mma.sync.aligned.m16n8k16.row.col.f32.f16.f16.f32 "
                 "{%0,%1,%2,%3}, {%4,%5,%6,%7}, {%8,%9}, {%0,%1,%2,%3};"
                 : "+f"(c[0]), "+f"(c[1]), "+f"(c[2]), "+f"(c[3])
                 : "r"(a[0]), "r"(a[1]), "r"(a[2]), "r"(a[3]), "r"(b[0]), "r"(b[1]));
}

__device__ __forceinline__ bool flag_ok(int flagsel) {
    if ((flagsel & 1) && g_flags[0] == 0) return false;
    if ((flagsel & 2) && g_flags[1] == 0) return false;
    return true;
}

// ---------------- flags ----------------
__global__ void reset_flags_kernel() { g_flags[0] = 0; g_flags[1] = 0; }

// ---------------- z-batched prep: conversions + nonzero scan ----------------
__global__ void prep_kernel(PrepBatch pb, const float4* __restrict__ scan_a,
                            const float4* __restrict__ scan_b) {
    const int z = blockIdx.z;
    const int mode = pb.mode[z];
    if (mode == 1) {
        const int total = (BDIM * DDIM) / 4;
        bool nzm = false, nzo = false;
        for (int i = blockIdx.x * blockDim.x + threadIdx.x; i < total;
             i += gridDim.x * blockDim.x) {
            float4 v = scan_a[i];
            nzm |= (v.x != 0.0f) | (v.y != 0.0f) | (v.z != 0.0f) | (v.w != 0.0f);
            float4 u = scan_b[i];
            nzo |= (u.x != 0.0f) | (u.y != 0.0f) | (u.z != 0.0f) | (u.w != 0.0f);
        }
        if (nzm) atomicOr(&g_flags[0], 1);
        if (nzo) atomicOr(&g_flags[1], 1);
        return;
    }
    const float4* __restrict__ src = pb.src[z];
    uint2* __restrict__ dst = pb.dst[z];
    const int n4 = pb.n4[z];
    for (int i = blockIdx.x * blockDim.x + threadIdx.x; i < n4; i += gridDim.x * blockDim.x) {
        float4 v = src[i];
        __half2 h0 = __floats2half2_rn(v.x, v.y);
        __half2 h1 = __floats2half2_rn(v.z, v.w);
        uint2 o;
        o.x = *(uint32_t*)&h0;
        o.y = *(uint32_t*)&h1;
        dst[i] = o;
    }
}

// ---------------- batched gated fp32 -> fp16 conversion ----------------
__global__ void conv_batch_kernel(ConvBatch cb) {
    const int z = blockIdx.z;
    if (!flag_ok(cb.flagsel[z])) return;
    const float4* __restrict__ src = cb.src[z];
    uint2* __restrict__ dst = cb.dst[z];
    const int n4 = cb.n4[z];
    for (int i = blockIdx.x * blockDim.x + threadIdx.x; i < n4; i += gridDim.x * blockDim.x) {
        float4 v = src[i];
        __half2 h0 = __floats2half2_rn(v.x, v.y);
        __half2 h1 = __floats2half2_rn(v.z, v.w);
        uint2 o;
        o.x = *(uint32_t*)&h0;
        o.y = *(uint32_t*)&h1;
        dst[i] = o;
    }
}

// ================= shared GEMM tiling constants =================
#define BK 64
#define CHUNKS (KDIM / BK)
#define STRB 144                            // bytes per k-row (64 halves + 8 pad)
#define NSTAGE 3

// ---------------- single-output fp16 GEMM (f32 accum) — gated/accum path ----
#define CTAM 128
#define CTAN 128
#define A_BYTES (CTAM * STRB)               // 18432
#define B_BYTES (CTAN * STRB)               // 18432
#define STAGE_BYTES (A_BYTES + B_BYTES)     // 36864
#define GEMM_SMEM (NSTAGE * STAGE_BYTES)    // 110592

__global__ __launch_bounds__(256, 2)
void gemm_fp16(const __half* __restrict__ A, GemmBatch gb)
{
    const int z = blockIdx.z;
    if (!flag_ok(gb.flagsel[z])) return;
    const __half* __restrict__ W = gb.W[z];
    float* __restrict__ C = gb.C[z];

    extern __shared__ char smem[];
    const uint32_t sb0 = smem_to_u32(smem);

    const int tid = threadIdx.x;
    const int wid = tid >> 5;
    const int lane = tid & 31;
    const int g = lane >> 2;
    const int t = lane & 3;
    const int wm = wid & 1;
    const int wn = wid >> 1;
    const int bm = blockIdx.y * CTAM;
    const int bn = blockIdx.x * CTAN;

    float c[4][4][4];
    #pragma unroll
    for (int i = 0; i < 4; i++)
        #pragma unroll
        for (int j = 0; j < 4; j++)
            #pragma unroll
            for (int q = 0; q < 4; q++) c[i][j][q] = 0.0f;

    const uint32_t a_row = (uint32_t)(wm * 64 + (lane & 15));
    const uint32_t a_kb  = (uint32_t)((lane >> 4) * 16);
    const uint32_t b_row = (uint32_t)(wn * 32 + (lane & 7) + ((lane & 16) ? 8 : 0));
    const uint32_t b_kb  = (uint32_t)((lane & 8) ? 16 : 0);

    auto load_chunk = [&](int stage, int kt) {
        const uint32_t sb = sb0 + (uint32_t)stage * STAGE_BYTES;
        #pragma unroll
        for (int i = 0; i < 4; i++) {
            int gr = tid + i * 256;
            int row = gr >> 3, c8 = gr & 7;
            cp16(sb + (uint32_t)(row * STRB + c8 * 16),
                 A + (size_t)(bm + row) * KDIM + kt + c8 * 8);
        }
        #pragma unroll
        for (int i = 0; i < 4; i++) {
            int gr = tid + i * 256;
            int row = gr >> 3, c8 = gr & 7;
            cp16(sb + (uint32_t)(A_BYTES + row * STRB + c8 * 16),
                 W + (size_t)(bn + row) * KDIM + kt + c8 * 8);
        }
        CP_COMMIT();
    };

    load_chunk(0, 0);
    load_chunk(1, BK);

    int stage = 0;
    for (int ch = 0; ch < CHUNKS; ch++) {
        if (ch + 2 < CHUNKS) {
            int ns = stage + 2; if (ns >= NSTAGE) ns -= NSTAGE;
            load_chunk(ns, (ch + 2) * BK);
            asm volatile("cp.async.wait_group 2;" ::: "memory");
        } else if (ch + 1 < CHUNKS) {
            asm volatile("cp.async.wait_group 1;" ::: "memory");
        } else {
            asm volatile("cp.async.wait_group 0;" ::: "memory");
        }
        __syncthreads();

        const uint32_t As = sb0 + (uint32_t)stage * STAGE_BYTES;
        const uint32_t Bs = As + A_BYTES;

        #pragma unroll
        for (int s = 0; s < 4; s++) {
            const uint32_t kb = (uint32_t)(s * 32);
            uint32_t a[4][4];
            #pragma unroll
            for (int mf = 0; mf < 4; mf++)
                ldm_x4(a[mf][0], a[mf][1], a[mf][2], a[mf][3],
                       As + (a_row + mf * 16) * STRB + kb + a_kb);
            uint32_t b[4][2];
            #pragma unroll
            for (int nh = 0; nh < 2; nh++) {
                uint32_t r0, r1, r2, r3;
                ldm_x4(r0, r1, r2, r3, Bs + (b_row + nh * 16) * STRB + kb + b_kb);
                b[2 * nh][0] = r0;      b[2 * nh][1] = r1;
                b[2 * nh + 1][0] = r2;  b[2 * nh + 1][1] = r3;
            }
            #pragma unroll
            for (int mf = 0; mf < 4; mf++)
                #pragma unroll
                for (int nf = 0; nf < 4; nf++)
                    mma_fp16(c[mf][nf], a[mf], b[nf]);
        }
        __syncthreads();
        if (++stage >= NSTAGE) stage = 0;
    }

    const float* b0 = gb.b0[z];
    const float* b1 = gb.b1[z];
    const float* b2 = gb.b2[z];
    const int accum = gb.accum;
    #pragma unroll
    for (int nf = 0; nf < 4; nf++) {
        const int col = bn + wn * 32 + nf * 8 + 2 * t;
        float bs0 = 0.0f, bs1 = 0.0f;
        if (!accum) {
            if (b0) { bs0 += b0[col]; bs1 += b0[col + 1]; }
            if (b1) { bs0 += b1[col]; bs1 += b1[col + 1]; }
            if (b2) { bs0 += b2[col]; bs1 += b2[col + 1]; }
        }
        #pragma unroll
        for (int mf = 0; mf < 4; mf++) {
            const int r = bm + wm * 64 + mf * 16 + g;
            float2 v0 = make_float2(c[mf][nf][0] + bs0, c[mf][nf][1] + bs1);
            float2 v1 = make_float2(c[mf][nf][2] + bs0, c[mf][nf][3] + bs1);
            float2* p0 = (float2*)(C + (size_t)r * DDIM + col);
            float2* p1 = (float2*)(C + (size_t)(r + 8) * DDIM + col);
            if (accum) {
                float2 o0 = *p0, o1 = *p1;
                v0.x += o0.x; v0.y += o0.y; v1.x += o1.x; v1.y += o1.y;
            }
            *p0 = v0;
            *p1 = v1;
        }
    }
}

// ---------------- dual-output GEMM: preA & preB in one CTA, fused final ----
// CTA tile 128(M) x 64(N) per output; 8 warps = 2(M) x 4(N), warp tile 64x16/output.
#define DCTAM 128
#define DCTAN 64
#define D_A_BYTES (DCTAM * STRB)                 // 18432
#define D_W_BYTES (DCTAN * STRB)                 // 9216
#define D_STAGE (D_A_BYTES + 2 * D_W_BYTES)      // 36864
#define DGEMM_SMEM (NSTAGE * D_STAGE)            // 110592

__global__ __launch_bounds__(256, 2)
void gemm_dual(const __half* __restrict__ A,
               const __half* __restrict__ W0, const __half* __restrict__ W1,
               float* __restrict__ preA, float* __restrict__ preB,
               const float* __restrict__ bA0, const float* __restrict__ bA1,
               const float* __restrict__ bB0, const float* __restrict__ bB1,
               const float* __restrict__ bB2,
               float* __restrict__ outp, const float* __restrict__ bdec)
{
    extern __shared__ char smem[];
    const uint32_t sb0 = smem_to_u32(smem);

    const int tid = threadIdx.x;
    const int wid = tid >> 5;
    const int lane = tid & 31;
    const int g = lane >> 2;
    const int t = lane & 3;
    const int wm = wid & 1;
    const int wn = wid >> 1;
    const int bm = blockIdx.y * DCTAM;
    const int bn = blockIdx.x * DCTAN;

    float cA[4][2][4], cB[4][2][4];
    #pragma unroll
    for (int i = 0; i < 4; i++)
        #pragma unroll
        for (int j = 0; j < 2; j++)
            #pragma unroll
            for (int q = 0; q < 4; q++) { cA[i][j][q] = 0.0f; cB[i][j][q] = 0.0f; }

    const uint32_t a_row = (uint32_t)(wm * 64 + (lane & 15));
    const uint32_t a_kb  = (uint32_t)((lane >> 4) * 16);
    const uint32_t b_row = (uint32_t)(wn * 16 + (lane & 7) + ((lane & 16) ? 8 : 0));
    const uint32_t b_kb  = (uint32_t)((lane & 8) ? 16 : 0);

    auto load_chunk = [&](int stage, int kt) {
        const uint32_t sb = sb0 + (uint32_t)stage * D_STAGE;
        #pragma unroll
        for (int i = 0; i < 4; i++) {                  // A: 1024 granules
            int gr = tid + i * 256;
            int row = gr >> 3, c8 = gr & 7;
            cp16(sb + (uint32_t)(row * STRB + c8 * 16),
                 A + (size_t)(bm + row) * KDIM + kt + c8 * 8);
        }
        #pragma unroll
        for (int i = 0; i < 2; i++) {                  // W0: 512 granules
            int gr = tid + i * 256;
            int row = gr >> 3, c8 = gr & 7;
            cp16(sb + (uint32_t)(D_A_BYTES + row * STRB + c8 * 16),
                 W0 + (size_t)(bn + row) * KDIM + kt + c8 * 8);
        }
        #pragma unroll
        for (int i = 0; i < 2; i++) {                  // W1: 512 granules
            int gr = tid + i * 256;
            int row = gr >> 3, c8 = gr & 7;
            cp16(sb + (uint32_t)(D_A_BYTES + D_W_BYTES + row * STRB + c8 * 16),
                 W1 + (size_t)(bn + row) * KDIM + kt + c8 * 8);
        }
        CP_COMMIT();
    };

    load_chunk(0, 0);
    load_chunk(1, BK);

    int stage = 0;
    for (int ch = 0; ch < CHUNKS; ch++) {
        if (ch + 2 < CHUNKS) {
            int ns = stage + 2; if (ns >= NSTAGE) ns -= NSTAGE;
            load_chunk(ns, (ch + 2) * BK);
            asm volatile("cp.async.wait_group 2;" ::: "memory");
        } else if (ch + 1 < CHUNKS) {
            asm volatile("cp.async.wait_group 1;" ::: "memory");
        } else {
            asm volatile("cp.async.wait_group 0;" ::: "memory");
        }
        __syncthreads();

        const uint32_t As  = sb0 + (uint32_t)stage * D_STAGE;
        const uint32_t Bs0 = As + D_A_BYTES;
        const uint32_t Bs1 = Bs0 + D_W_BYTES;

        #pragma unroll
        for (int s = 0; s < 4; s++) {
            const uint32_t kb = (uint32_t)(s * 32);
            uint32_t a[4][4];
            #pragma unroll
            for (int mf = 0; mf < 4; mf++)
                ldm_x4(a[mf][0], a[mf][1], a[mf][2], a[mf][3],
                       As + (a_row + mf * 16) * STRB + kb + a_kb);
            uint32_t b0[2][2], b1[2][2];
            {
                uint32_t r0, r1, r2, r3;
                ldm_x4(r0, r1, r2, r3, Bs0 + b_row * STRB + kb + b_kb);
                b0[0][0] = r0; b0[0][1] = r1; b0[1][0] = r2; b0[1][1] = r3;
                ldm_x4(r0, r1, r2, r3, Bs1 + b_row * STRB + kb + b_kb);
                b1[0][0] = r0; b1[0][1] = r1; b1[1][0] = r2; b1[1][1] = r3;
            }
            #pragma unroll
            for (int mf = 0; mf < 4; mf++)
                #pragma unroll
                for (int nf = 0; nf < 2; nf++) {
                    mma_fp16(cA[mf][nf], a[mf], b0[nf]);
                    mma_fp16(cB[mf][nf], a[mf], b1[nf]);
                }
        }
        __syncthreads();
        if (++stage >= NSTAGE) stage = 0;
    }

    // ---- fused epilogue ----
    const bool slow = (g_flags[0] | g_flags[1]) != 0;
    #pragma unroll
    for (int nf = 0; nf < 2; nf++) {
        const int col = bn + wn * 16 + nf * 8 + 2 * t;
        const float bsA0 = bA0[col] + bA1[col];
        const float bsA1 = bA0[col + 1] + bA1[col + 1];
        const float bsB0 = bB0[col] + bB1[col] + bB2[col];
        const float bsB1 = bB0[col + 1] + bB1[col + 1] + bB2[col + 1];
        const float d0 = bdec[col], d1 = bdec[col + 1];
        #pragma unroll
        for (int mf = 0; mf < 4; mf++) {
            const int r = bm + wm * 64 + mf * 16 + g;
            float2 va0 = make_float2(cA[mf][nf][0] + bsA0, cA[mf][nf][1] + bsA1);
            float2 va1 = make_float2(cA[mf][nf][2] + bsA0, cA[mf][nf][3] + bsA1);
            float2 vb0 = make_float2(cB[mf][nf][0] + bsB0, cB[mf][nf][1] + bsB1);
            float2 vb1 = make_float2(cB[mf][nf][2] + bsB0, cB[mf][nf][3] + bsB1);
            if (slow) {
                *(float2*)(preA + (size_t)r * DDIM + col) = va0;
                *(float2*)(preA + (size_t)(r + 8) * DDIM + col) = va1;
                *(float2*)(preB + (size_t)r * DDIM + col) = vb0;
                *(float2*)(preB + (size_t)(r + 8) * DDIM + col) = vb1;
            } else {
                float2 o0, o1;
                o0.x = d0 + sigmoidf_(va0.x) * sigmoidf_(vb0.x);
                o0.y = d1 + sigmoidf_(va0.y) * sigmoidf_(vb0.y);
                o1.x = d0 + sigmoidf_(va1.x) * sigmoidf_(vb1.x);
                o1.y = d1 + sigmoidf_(va1.y) * sigmoidf_(vb1.y);
                *(float2*)(outp + (size_t)r * DDIM + col) = o0;
                *(float2*)(outp + (size_t)(r + 8) * DDIM + col) = o1;
            }
        }
    }
}

// ---------------- gated elementwise ----------------
__global__ void rgconv_kernel(const float4* __restrict__ mem0, uint2* __restrict__ ay) {
    if (g_flags[0] == 0) return;
    const int n4 = (BDIM * DDIM) / 4;
    const float4* __restrict__ pc = (const float4*)g_preC;
    for (int i = blockIdx.x * blockDim.x + threadIdx.x; i < n4; i += gridDim.x * blockDim.x) {
        float4 p = pc[i];
        float4 m = mem0[i];
        __half2 h0 = __floats2half2_rn(sigmoidf_(p.x) * m.x, sigmoidf_(p.y) * m.y);
        __half2 h1 = __floats2half2_rn(sigmoidf_(p.z) * m.z, sigmoidf_(p.w) * m.w);
        uint2 o;
        o.x = *(uint32_t*)&h0;
        o.y = *(uint32_t*)&h1;
        ay[i] = o;
    }
}

__global__ void final_kernel(float* __restrict__ out, const float* __restrict__ b_dec) {
    if (g_flags[0] == 0 && g_flags[1] == 0) return;
    const bool usemem = (g_flags[0] != 0);
    const int total = BDIM * DDIM;
    for (int i = blockIdx.x * blockDim.x + threadIdx.x; i < total; i += gridDim.x * blockDim.x) {
        float d = usemem ? g_dec[i] : b_dec[i & (DDIM - 1)];
        out[i] = d + sigmoidf_(g_preA[i]) * sigmoidf_(g_preB[i]);
    }
}

// ---------------- host orchestration ----------------
extern "C" void kernel_launch(void* const* d_in, const int* in_sizes, int n_in,
                              void* d_out, int out_size) {
    const float* x              = (const float*)d_in[0];
    const float* out0           = (const float*)d_in[1];
    const float* mem0           = (const float*)d_in[2];
    const float* w_inpgate      = (const float*)d_in[3];
    const float* b_inpgate      = (const float*)d_in[4];
    const float* w_rec_inpgate  = (const float*)d_in[5];
    const float* b_rec_inpgate  = (const float*)d_in[6];
    const float* w_mem_inpgate  = (const float*)d_in[7];
    const float* b_mem_inpgate  = (const float*)d_in[8];
    const float* w_inp          = (const float*)d_in[9];
    const float* b_inp          = (const float*)d_in[10];
    const float* w_rec_inp      = (const float*)d_in[11];
    const float* b_rec_inp      = (const float*)d_in[12];
    const float* w_readgate     = (const float*)d_in[13];
    const float* b_readgate     = (const float*)d_in[14];
    const float* w_rec_readgate = (const float*)d_in[15];
    const float* b_rec_readgate = (const float*)d_in[16];
    const float* w_mem_readgate = (const float*)d_in[17];
    const float* b_mem_readgate = (const float*)d_in[18];
    const float* w_decoder      = (const float*)d_in[19];
    const float* b_decoder      = (const float*)d_in[20];
    float* out = (float*)d_out;

    void *pA, *pB, *pC, *pD, *pax, *pay, *pw0, *pw1, *pw2;
    cudaGetSymbolAddress(&pA, g_preA); cudaGetSymbolAddress(&pB, g_preB);
    cudaGetSymbolAddress(&pC, g_preC); cudaGetSymbolAddress(&pD, g_dec);
    cudaGetSymbolAddress(&pax, g_ax);  cudaGetSymbolAddress(&pay, g_ay);
    cudaGetSymbolAddress(&pw0, g_w0);  cudaGetSymbolAddress(&pw1, g_w1);
    cudaGetSymbolAddress(&pw2, g_w2);
    float* preA = (float*)pA;  float* preB = (float*)pB;
    float* preC = (float*)pC;  float* dec  = (float*)pD;
    __half* ax = (__half*)pax; __half* ay = (__half*)pay;
    __half* w0h = (__half*)pw0; __half* w1h = (__half*)pw1; __half* w2h = (__half*)pw2;

    cudaFuncSetAttribute(gemm_fp16, cudaFuncAttributeMaxDynamicSharedMemorySize, GEMM_SMEM);
    cudaFuncSetAttribute(gemm_dual, cudaFuncAttributeMaxDynamicSharedMemorySize, DGEMM_SMEM);

    const int nA4 = (BDIM * KDIM) / 4;
    const int nW4 = (DDIM * KDIM) / 4;
    const dim3 GRID1(DDIM / CTAN, BDIM / CTAM, 1);   // 16 x 32
    const dim3 GRID2(DDIM / CTAN, BDIM / CTAM, 2);
    const dim3 GRID3(DDIM / CTAN, BDIM / CTAM, 3);
    const dim3 DGRID(DDIM / DCTAN, BDIM / DCTAM, 1); // 32 x 32

    // 1) reset flags
    reset_flags_kernel<<<1, 1>>>();

    // 2) one prep launch: x conv | scan | 3 weight convs
    {
        PrepBatch pb = {};
        pb.src[0] = (const float4*)x;          pb.dst[0] = (uint2*)ax;  pb.n4[0] = nA4; pb.mode[0] = 0;
        pb.mode[1] = 1;                        // scan mem0/out0
        pb.src[2] = (const float4*)w_inp;      pb.dst[2] = (uint2*)w0h; pb.n4[2] = nW4; pb.mode[2] = 0;
        pb.src[3] = (const float4*)w_inpgate;  pb.dst[3] = (uint2*)w1h; pb.n4[3] = nW4; pb.mode[3] = 0;
        pb.src[4] = (const float4*)w_readgate; pb.dst[4] = (uint2*)w2h; pb.n4[4] = nW4; pb.mode[4] = 0;
        prep_kernel<<<dim3(512, 1, 5), 256>>>(pb, (const float4*)mem0, (const float4*)out0);
    }

    // 3) dual GEMM: preA + preB, fused final fast path
    gemm_dual<<<DGRID, 256, DGEMM_SMEM>>>(ax, w0h, w1h, preA, preB,
                                          b_inp, b_rec_inp,
                                          b_inpgate, b_mem_inpgate, b_rec_inpgate,
                                          out, b_decoder);

    // 4) preC GEMM (mem0 gated)
    {
        GemmBatch gb = {};
        gb.W[0] = w2h; gb.C[0] = preC;
        gb.b0[0] = b_readgate; gb.b1[0] = b_mem_readgate; gb.b2[0] = b_rec_readgate;
        gb.flagsel[0] = 1; gb.accum = 0;
        gemm_fp16<<<GRID1, 256, GEMM_SMEM>>>(ax, gb);
    }

    // 5) out0 recurrent terms  [out0 != 0]
    {
        ConvBatch cb = {};
        cb.src[0] = (const float4*)out0;            cb.dst[0] = (uint2*)ay;  cb.n4[0] = nA4; cb.flagsel[0] = 2;
        cb.src[1] = (const float4*)w_rec_inp;       cb.dst[1] = (uint2*)w0h; cb.n4[1] = nW4; cb.flagsel[1] = 2;
        cb.src[2] = (const float4*)w_rec_inpgate;   cb.dst[2] = (uint2*)w1h; cb.n4[2] = nW4; cb.flagsel[2] = 2;
        cb.src[3] = (const float4*)w_rec_readgate;  cb.dst[3] = (uint2*)w2h; cb.n4[3] = nW4; cb.flagsel[3] = 3;
        conv_batch_kernel<<<dim3(512, 1, 4), 256>>>(cb);
    }
    {
        GemmBatch gb = {};
        gb.W[0] = w0h; gb.C[0] = preA; gb.flagsel[0] = 2;
        gb.W[1] = w1h; gb.C[1] = preB; gb.flagsel[1] = 2;
        gb.W[2] = w2h; gb.C[2] = preC; gb.flagsel[2] = 3;
        gb.accum = 1;
        gemm_fp16<<<GRID3, 256, GEMM_SMEM>>>(ay, gb);
    }

    // 6) mem0 terms  [mem0 != 0]
    {
        ConvBatch cb = {};
        cb.src[0] = (const float4*)mem0;            cb.dst[0] = (uint2*)ay;  cb.n4[0] = nA4; cb.flagsel[0] = 1;
        cb.src[1] = (const float4*)w_mem_inpgate;   cb.dst[1] = (uint2*)w0h; cb.n4[1] = nW4; cb.flagsel[1] = 1;
        cb.src[2] = (const float4*)w_mem_readgate;  cb.dst[2] = (uint2*)w1h; cb.n4[2] = nW4; cb.flagsel[2] = 1;
        conv_batch_kernel<<<dim3(512, 1, 3), 256>>>(cb);
    }
    {
        GemmBatch gb = {};
        gb.W[0] = w0h; gb.C[0] = preB; gb.flagsel[0] = 1;
        gb.W[1] = w1h; gb.C[1] = preC; gb.flagsel[1] = 1;
        gb.accum = 1;
        gemm_fp16<<<GRID2, 256, GEMM_SMEM>>>(ay, gb);
    }

    // 7) ay = fp16(sigmoid(preC)*mem0), convert w_decoder, decoder GEMM  [mem0 != 0]
    rgconv_kernel<<<2048, 256>>>((const float4*)mem0, (uint2*)ay);
    {
        ConvBatch cb = {};
        cb.src[0] = (const float4*)w_decoder; cb.dst[0] = (uint2*)w0h; cb.n4[0] = nW4; cb.flagsel[0] = 1;
        conv_batch_kernel<<<dim3(512, 1, 1), 256>>>(cb);
    }
    {
        GemmBatch gb = {};
        gb.W[0] = w0h; gb.C[0] = dec; gb.b0[0] = b_decoder; gb.flagsel[0] = 1;
        gb.accum = 0;
        gemm_fp16<<<GRID1, 256, GEMM_SMEM>>>(ay, gb);
    }

    // 8) slow-path final (no-op when both states are zero)
    final_kernel<<<2048, 256>>>(out, b_decoder);
}